// round 1
// baseline (speedup 1.0000x reference)
#include <cuda_runtime.h>
#include <math.h>

// Problem constants (fixed by the bench: B=8, H=W=128, C=192, split=(8,16), heads=8)
#define BB   8
#define HH   128
#define WW   128
#define CC   192
#define LL   (HH * WW)          // 16384
#define MM   (BB * LL)          // 131072 rows
#define CHH  96                 // C/2 per branch
#define NHH  4                  // heads per branch
#define DD   24                 // head dim
#define EPSV 1e-5f
#define SCALE 0.20412414523193154f   // 24^-0.5

// ---------------------------------------------------------------------------
// Scratch arena (no allocations allowed). Offsets in floats.
//   q1   : MM*CC
//   v1   : MM*CC
//   k2   : MM*CC
//   v2   : MM*CC
//   att  : MM*CC
//   conv : MM*CC
//   hid  : MM*96
//   gate : MM
//   w1t  : 192*96
// ---------------------------------------------------------------------------
#define OFF_Q1   ((size_t)0)
#define OFF_V1   (OFF_Q1  + (size_t)MM * CC)
#define OFF_K2   (OFF_V1  + (size_t)MM * CC)
#define OFF_V2   (OFF_K2  + (size_t)MM * CC)
#define OFF_ATT  (OFF_V2  + (size_t)MM * CC)
#define OFF_CONV (OFF_ATT + (size_t)MM * CC)
#define OFF_HID  (OFF_CONV + (size_t)MM * CC)
#define OFF_GATE (OFF_HID + (size_t)MM * 96)
#define OFF_W1T  (OFF_GATE + (size_t)MM)
#define SCRATCH_FLOATS (OFF_W1T + (size_t)192 * 96)

__device__ float g_scratch[SCRATCH_FLOATS];

// ---------------------------------------------------------------------------
// Generic SGEMM, K fixed at 192. C[m,n] = gate[m] * (A[m,:] @ B[:,n]) + bias[n]
// A: M x 192 row-major (lda). B: 192 x N row-major (ldb), pointer may be
// pre-offset into a wider matrix. 64x64 tile, BK=16, 256 threads, 4x4 micro.
// ---------------------------------------------------------------------------
__global__ __launch_bounds__(256) void sgemm192(
    const float* __restrict__ A, int lda,
    const float* __restrict__ Bm, int ldb,
    const float* __restrict__ bias,
    const float* __restrict__ gate,
    float* __restrict__ Cout, int ldc, int N)
{
    __shared__ float As[16][65];   // padded, stored transposed
    __shared__ float Bs[16][64];

    const int bm = blockIdx.x * 64;
    const int bn = blockIdx.y * 64;
    const int tid = threadIdx.x;

    const int arow = tid >> 2;             // 0..63
    const int acol = (tid & 3) << 2;       // 0,4,8,12
    const int brow = tid >> 4;             // 0..15
    const int bcol = (tid & 15) << 2;      // 0..60
    const int tx = tid & 15;               // n direction
    const int ty = tid >> 4;               // m direction

    float acc[4][4] = {};

    const float* Aptr = A + (size_t)(bm + arow) * lda + acol;

    for (int k0 = 0; k0 < 192; k0 += 16) {
        float4 av = *(const float4*)(Aptr + k0);
        As[acol + 0][arow] = av.x;
        As[acol + 1][arow] = av.y;
        As[acol + 2][arow] = av.z;
        As[acol + 3][arow] = av.w;

        float4 bv = make_float4(0.f, 0.f, 0.f, 0.f);
        if (bn + bcol < N)
            bv = *(const float4*)&Bm[(size_t)(k0 + brow) * ldb + bn + bcol];
        *(float4*)&Bs[brow][bcol] = bv;

        __syncthreads();

        #pragma unroll
        for (int k = 0; k < 16; k++) {
            float a0 = As[k][ty * 4 + 0];
            float a1 = As[k][ty * 4 + 1];
            float a2 = As[k][ty * 4 + 2];
            float a3 = As[k][ty * 4 + 3];
            float4 bq = *(const float4*)&Bs[k][tx * 4];
            acc[0][0] += a0 * bq.x; acc[0][1] += a0 * bq.y; acc[0][2] += a0 * bq.z; acc[0][3] += a0 * bq.w;
            acc[1][0] += a1 * bq.x; acc[1][1] += a1 * bq.y; acc[1][2] += a1 * bq.z; acc[1][3] += a1 * bq.w;
            acc[2][0] += a2 * bq.x; acc[2][1] += a2 * bq.y; acc[2][2] += a2 * bq.z; acc[2][3] += a2 * bq.w;
            acc[3][0] += a3 * bq.x; acc[3][1] += a3 * bq.y; acc[3][2] += a3 * bq.z; acc[3][3] += a3 * bq.w;
        }
        __syncthreads();
    }

    const int n = bn + tx * 4;
    if (n < N) {
        float bx = bias ? bias[n + 0] : 0.f;
        float by = bias ? bias[n + 1] : 0.f;
        float bz = bias ? bias[n + 2] : 0.f;
        float bw = bias ? bias[n + 3] : 0.f;
        #pragma unroll
        for (int i = 0; i < 4; i++) {
            int m = bm + ty * 4 + i;
            float g = gate ? gate[m] : 1.0f;
            float4 o;
            o.x = acc[i][0] * g + bx;
            o.y = acc[i][1] * g + by;
            o.z = acc[i][2] * g + bz;
            o.w = acc[i][3] * g + bw;
            *(float4*)&Cout[(size_t)m * ldc + n] = o;
        }
    }
}

// ---------------------------------------------------------------------------
// Window attention. One block = (window, head, batch*branch).
// 128 tokens per window (8x16 or 16x8), head dim 24, online softmax.
// q from x-qkv, k from y-qkv, v from x-qkv. Writes att (B,L,C) directly.
// ---------------------------------------------------------------------------
__global__ __launch_bounds__(128) void win_attn(
    const float* __restrict__ q, const float* __restrict__ k,
    const float* __restrict__ v, float* __restrict__ out)
{
    __shared__ float Ks[128][DD];
    __shared__ float Vs[128][DD];

    const int wid  = blockIdx.x;      // 0..127 window within image+branch
    const int head = blockIdx.y;      // 0..3
    const int z    = blockIdx.z;      // 0..15
    const int b  = z >> 1;
    const int br = z & 1;

    const int Hs  = br ? 16 : 8;
    const int Wsp = br ? 8 : 16;
    const int nWw = WW / Wsp;
    const int wy = wid / nWw, wx = wid % nWw;
    const int h0 = wy * Hs, w0 = wx * Wsp;
    const int cb = br * CHH + head * DD;
    const int tid = threadIdx.x;

    // cooperative K,V load
    for (int idx = tid; idx < 128 * DD; idx += 128) {
        int t = idx / DD, d = idx - t * DD;
        int hs = t / Wsp, ws = t - hs * Wsp;
        int l = (h0 + hs) * WW + (w0 + ws);
        size_t base = ((size_t)b * LL + l) * CC + cb + d;
        Ks[t][d] = k[base];
        Vs[t][d] = v[base];
    }
    __syncthreads();

    // own query row
    const int hs = tid / Wsp, ws = tid - hs * Wsp;
    const int l = (h0 + hs) * WW + (w0 + ws);
    const size_t qbase = ((size_t)b * LL + l) * CC + cb;

    float qreg[DD];
    #pragma unroll
    for (int d = 0; d < DD; d++) qreg[d] = q[qbase + d] * SCALE;

    float mrun = -1e30f, lsum = 0.f;
    float acc[DD];
    #pragma unroll
    for (int d = 0; d < DD; d++) acc[d] = 0.f;

    for (int j = 0; j < 128; j++) {
        float s = 0.f;
        #pragma unroll
        for (int d = 0; d < DD; d++) s += qreg[d] * Ks[j][d];
        if (s > mrun) {                       // rare after warm-up
            float corr = __expf(mrun - s);
            lsum *= corr;
            #pragma unroll
            for (int d = 0; d < DD; d++) acc[d] *= corr;
            mrun = s;
        }
        float p = __expf(s - mrun);
        lsum += p;
        #pragma unroll
        for (int d = 0; d < DD; d++) acc[d] += p * Vs[j][d];
    }

    float inv = 1.f / lsum;
    #pragma unroll
    for (int d = 0; d < DD; d++) out[qbase + d] = acc[d] * inv;
}

// ---------------------------------------------------------------------------
// Depthwise 3x3 conv (SAME) + bias + BN + exact GELU, channel-last layout.
// ---------------------------------------------------------------------------
__global__ __launch_bounds__(256) void dwconv_bn_gelu(
    const float* __restrict__ x, const float* __restrict__ wgt,
    const float* __restrict__ wb,
    const float* __restrict__ g1, const float* __restrict__ b1,
    const float* __restrict__ m1, const float* __restrict__ v1r,
    float* __restrict__ out)
{
    int idx = blockIdx.x * 256 + threadIdx.x;
    if (idx >= MM * CC) return;
    int c = idx % CC;
    int rem = idx / CC;
    int l = rem % LL;
    int b = rem / LL;
    int h = l >> 7, w = l & 127;

    float acc = 0.f;
    #pragma unroll
    for (int kh = 0; kh < 3; kh++) {
        int hh = h + kh - 1;
        if ((unsigned)hh >= (unsigned)HH) continue;
        #pragma unroll
        for (int kw = 0; kw < 3; kw++) {
            int ww = w + kw - 1;
            if ((unsigned)ww >= (unsigned)WW) continue;
            acc += x[((size_t)b * LL + hh * WW + ww) * CC + c] * wgt[c * 9 + kh * 3 + kw];
        }
    }
    acc += wb[c];
    float sc = g1[c] * rsqrtf(v1r[c] + EPSV);
    float t = (acc - m1[c]) * sc + b1[c];
    out[idx] = 0.5f * t * (1.f + erff(t * 0.70710678118654752f));
}

// ---------------------------------------------------------------------------
// Transpose si_w1 (96,192) -> (192,96) so the 1x1 conv runs through sgemm192.
// ---------------------------------------------------------------------------
__global__ void transpose_w1(const float* __restrict__ w1, float* __restrict__ w1t)
{
    int idx = blockIdx.x * 256 + threadIdx.x;
    if (idx >= 96 * 192) return;
    int j = idx / 192, c = idx - j * 192;
    w1t[c * 96 + j] = w1[idx];
}

// ---------------------------------------------------------------------------
// gate[m] = sigmoid( sum_j si_w2[j] * gelu(bn2(hid[m,j])) + si_b2 )
// One warp per pixel (hid already includes si_b1 via GEMM bias).
// ---------------------------------------------------------------------------
__global__ __launch_bounds__(128) void gate_kernel(
    const float* __restrict__ hid,
    const float* __restrict__ g2, const float* __restrict__ b2,
    const float* __restrict__ m2, const float* __restrict__ v2r,
    const float* __restrict__ w2, const float* __restrict__ sb2,
    float* __restrict__ gate)
{
    int m = blockIdx.x * 4 + (threadIdx.x >> 5);
    int lane = threadIdx.x & 31;
    float sum = 0.f;
    #pragma unroll
    for (int jj = 0; jj < 3; jj++) {
        int j = lane + jj * 32;
        float t = hid[(size_t)m * 96 + j];
        float sc = g2[j] * rsqrtf(v2r[j] + EPSV);
        t = (t - m2[j]) * sc + b2[j];
        t = 0.5f * t * (1.f + erff(t * 0.70710678118654752f));
        sum += t * w2[j];
    }
    #pragma unroll
    for (int o = 16; o; o >>= 1) sum += __shfl_xor_sync(0xffffffffu, sum, o);
    if (lane == 0) {
        float s = sum + sb2[0];
        gate[m] = 1.f / (1.f + __expf(-s));
    }
}

// ---------------------------------------------------------------------------
extern "C" void kernel_launch(void* const* d_in, const int* in_sizes, int n_in,
                              void* d_out, int out_size)
{
    const float* x     = (const float*)d_in[0];
    const float* y     = (const float*)d_in[1];
    const float* Wqkv  = (const float*)d_in[2];
    const float* bqkv  = (const float*)d_in[3];
    const float* dw_w  = (const float*)d_in[4];
    const float* dw_b  = (const float*)d_in[5];
    const float* bn1_g = (const float*)d_in[6];
    const float* bn1_b = (const float*)d_in[7];
    const float* bn1_m = (const float*)d_in[8];
    const float* bn1_v = (const float*)d_in[9];
    const float* si_w1 = (const float*)d_in[10];
    const float* si_b1 = (const float*)d_in[11];
    const float* bn2_g = (const float*)d_in[12];
    const float* bn2_b = (const float*)d_in[13];
    const float* bn2_m = (const float*)d_in[14];
    const float* bn2_v = (const float*)d_in[15];
    const float* si_w2 = (const float*)d_in[16];
    const float* si_b2 = (const float*)d_in[17];
    const float* projw = (const float*)d_in[18];
    const float* projb = (const float*)d_in[19];

    float* scratch = nullptr;
    cudaGetSymbolAddress((void**)&scratch, g_scratch);

    float* q1   = scratch + OFF_Q1;
    float* v1   = scratch + OFF_V1;
    float* k2   = scratch + OFF_K2;
    float* v2   = scratch + OFF_V2;
    float* att  = scratch + OFF_ATT;
    float* conv = scratch + OFF_CONV;
    float* hid  = scratch + OFF_HID;
    float* gate = scratch + OFF_GATE;
    float* w1t  = scratch + OFF_W1T;

    dim3 gemmGrid(MM / 64, 3);

    // qkv projections (only the 4 needed slices)
    sgemm192<<<gemmGrid, 256>>>(x, CC, Wqkv + 0,       3 * CC, bqkv + 0,       nullptr, q1, CC, CC);
    sgemm192<<<gemmGrid, 256>>>(x, CC, Wqkv + 2 * CC,  3 * CC, bqkv + 2 * CC,  nullptr, v1, CC, CC);
    sgemm192<<<gemmGrid, 256>>>(y, CC, Wqkv + CC,      3 * CC, bqkv + CC,      nullptr, k2, CC, CC);
    sgemm192<<<gemmGrid, 256>>>(y, CC, Wqkv + 2 * CC,  3 * CC, bqkv + 2 * CC,  nullptr, v2, CC, CC);

    // window attention (both branches, all heads)
    win_attn<<<dim3(128, NHH, BB * 2), 128>>>(q1, k2, v1, att);

    // conv gating path on v2
    dwconv_bn_gelu<<<(MM * CC + 255) / 256, 256>>>(v2, dw_w, dw_b,
                                                   bn1_g, bn1_b, bn1_m, bn1_v, conv);
    transpose_w1<<<(96 * 192 + 255) / 256, 256>>>(si_w1, w1t);
    sgemm192<<<dim3(MM / 64, 2), 256>>>(conv, CC, w1t, 96, si_b1, nullptr, hid, 96, 96);
    gate_kernel<<<MM / 4, 128>>>(hid, bn2_g, bn2_b, bn2_m, bn2_v, si_w2, si_b2, gate);

    // final projection with fused per-row sigmoid gate
    sgemm192<<<gemmGrid, 256>>>(att, CC, projw, CC, projb, gate, (float*)d_out, CC, CC);
}